// round 8
// baseline (speedup 1.0000x reference)
#include <cuda_runtime.h>
#include <cuda_bf16.h>
#include <cstdint>

#define NTOK 16384
#define HDIM 4096
#define NEXP 64
#define TOPK 2

#define BM 128
#define BK 64
#define NCHUNK (HDIM / BK)    // 64
#define THREADS 256

// x bf16 tiles: 128 rows x 128B (64 bf16), 16B cells XOR-swizzled; 2 stages each
#define XSTG 16384
#define OFF_XH 0
#define OFF_XL (2 * XSTG)               // 32768
// W bf16 tiles: 64 rows x 144B (128B data + 16B pad); 4 stages each
#define WROW_B 144
#define WTILE_B (NEXP * WROW_B)         // 9216
#define OFF_WH (4 * XSTG)               // 65536
#define OFF_WL (OFF_WH + 4 * WTILE_B)   // 102400
#define SMEM_B (OFF_WL + 4 * WTILE_B)   // 139264

__device__ __nv_bfloat16 g_Wh[NEXP * HDIM];
__device__ __nv_bfloat16 g_Wl[NEXP * HDIM];

__device__ __forceinline__ uint32_t smem_u32(const void* p) {
    uint32_t a;
    asm("{ .reg .u64 t; cvta.to.shared.u64 t, %1; cvt.u32.u64 %0, t; }" : "=r"(a) : "l"(p));
    return a;
}

__device__ __forceinline__ void cpa16(uint32_t dst, const void* src) {
    asm volatile("cp.async.cg.shared.global [%0], [%1], 16;" :: "r"(dst), "l"(src) : "memory");
}

__device__ __forceinline__ void ldm4(uint32_t addr, uint32_t* r) {
    asm volatile("ldmatrix.sync.aligned.m8n8.x4.shared.b16 {%0,%1,%2,%3}, [%4];"
                 : "=r"(r[0]), "=r"(r[1]), "=r"(r[2]), "=r"(r[3]) : "r"(addr));
}

__device__ __forceinline__ void sts128(uint32_t addr, uint32_t a, uint32_t b,
                                       uint32_t c, uint32_t d) {
    asm volatile("st.shared.v4.b32 [%0], {%1,%2,%3,%4};"
                 :: "r"(addr), "r"(a), "r"(b), "r"(c), "r"(d) : "memory");
}

// split f32 pair into bf16x2 hi + bf16x2 lo (element0 in lo16)
__device__ __forceinline__ void split_pair(float f0, float f1, uint32_t& hi, uint32_t& lo) {
    asm("cvt.rn.bf16x2.f32 %0, %1, %2;" : "=r"(hi) : "f"(f1), "f"(f0));
    float h0 = __uint_as_float(hi << 16);
    float h1 = __uint_as_float(hi & 0xFFFF0000u);
    float l0 = f0 - h0;
    float l1 = f1 - h1;
    asm("cvt.rn.bf16x2.f32 %0, %1, %2;" : "=r"(lo) : "f"(l1), "f"(l0));
}

__device__ __forceinline__ void mma_bf16(float* d, const uint32_t* a, const uint32_t* b) {
    asm volatile(
        "mma.sync.aligned.m16n8k16.row.col.f32.bf16.bf16.f32 "
        "{%0,%1,%2,%3}, {%4,%5,%6,%7}, {%8,%9}, {%0,%1,%2,%3};"
        : "+f"(d[0]), "+f"(d[1]), "+f"(d[2]), "+f"(d[3])
        : "r"(a[0]), "r"(a[1]), "r"(a[2]), "r"(a[3]), "r"(b[0]), "r"(b[1]));
}

__global__ void wsplit_kernel(const float* __restrict__ W) {
    int i = blockIdx.x * blockDim.x + threadIdx.x;
    float w = W[i];
    __nv_bfloat16 h = __float2bfloat16(w);
    g_Wh[i] = h;
    g_Wl[i] = __float2bfloat16(w - __bfloat162float(h));
}

__device__ __forceinline__ void issueW(uint32_t sbase, int c, int tid) {
    const int s = c & 3;
    const int k0 = c * BK;
#pragma unroll
    for (int j = 0; j < 2; j++) {            // 512 16B units each for Wh, Wl
        int u = tid + j * THREADS;
        int row = u >> 3, q = u & 7;
        cpa16(sbase + OFF_WH + s * WTILE_B + row * WROW_B + q * 16,
              g_Wh + (size_t)row * HDIM + k0 + q * 8);
        cpa16(sbase + OFF_WL + s * WTILE_B + row * WROW_B + q * 16,
              g_Wl + (size_t)row * HDIM + k0 + q * 8);
    }
    asm volatile("cp.async.commit_group;" ::: "memory");
}

__global__ __launch_bounds__(THREADS, 1)
void router_mma(const float* __restrict__ x,
                float* __restrict__ out_scores,
                float* __restrict__ out_w,
                float* __restrict__ out_e) {
    extern __shared__ char smem[];
    const uint32_t sbase = smem_u32(smem);
    const int tid = threadIdx.x;
    const int lane = tid & 31;
    const int wid = tid >> 5;        // 8 warps: wTok = wid>>1 (32 rows), wExp = wid&1 (32 experts)
    const int g = lane >> 2;
    const int t = lane & 3;
    const int rowBase = blockIdx.x * BM;
    const int tokRow0 = (wid >> 1) * 32;
    const int expCol0 = (wid & 1) * 32;
    const int rr = lane & 7;
    const int mtx = lane >> 3;

    // ldmatrix lane offsets
    const uint32_t w_lane_off =
        (uint32_t)(((mtx >> 1) * 8 + rr) * WROW_B + (mtx & 1) * 16);
    // x: row within tile per mt; cell column = ks*2 + (mtx>>1), XOR (row&7)
    const int xrow0 = tokRow0 + (mtx & 1) * 8 + rr;        // mt=0
    const int xcellb = mtx >> 1;

    // x LDG->split->STS staging: thread owns row tid>>1, half tid&1 (32 f32)
    const int srow = tid >> 1, shalf = tid & 1;
    const float* xg = x + (size_t)(rowBase + srow) * HDIM + shalf * 32;
    float4 st[8];

    float acc[2][4][4] = {};

    // ---- prologue ----
    issueW(sbase, 0, tid);
    issueW(sbase, 1, tid);
    issueW(sbase, 2, tid);

#pragma unroll
    for (int j = 0; j < 8; j++) st[j] = *(const float4*)(xg + j * 4);   // chunk 0
    {
        // split chunk 0 into stage 0
        const uint32_t xh = sbase + OFF_XH;
        const uint32_t xl = sbase + OFF_XL;
#pragma unroll
        for (int j = 0; j < 4; j++) {
            uint32_t h0, l0, h1, l1, h2, l2, h3, l3;
            split_pair(st[2 * j].x, st[2 * j].y, h0, l0);
            split_pair(st[2 * j].z, st[2 * j].w, h1, l1);
            split_pair(st[2 * j + 1].x, st[2 * j + 1].y, h2, l2);
            split_pair(st[2 * j + 1].z, st[2 * j + 1].w, h3, l3);
            uint32_t off = srow * 128 + ((((uint32_t)(shalf * 4 + j)) ^ (srow & 7)) << 4);
            sts128(xh + off, h0, h1, h2, h3);
            sts128(xl + off, l0, l1, l2, l3);
        }
    }
#pragma unroll
    for (int j = 0; j < 8; j++) st[j] = *(const float4*)(xg + BK + j * 4);  // chunk 1

    for (int c = 0; c < NCHUNK; c++) {
        if (c <= NCHUNK - 3) {
            asm volatile("cp.async.wait_group 2;" ::: "memory");
        } else if (c == NCHUNK - 2) {
            asm volatile("cp.async.wait_group 1;" ::: "memory");
        } else {
            asm volatile("cp.async.wait_group 0;" ::: "memory");
        }
        __syncthreads();

        if (c + 3 < NCHUNK) issueW(sbase, c + 3, tid);

        // ---- compute chunk c ----
        const uint32_t xh = sbase + OFF_XH + (c & 1) * XSTG;
        const uint32_t xl = sbase + OFF_XL + (c & 1) * XSTG;
        const uint32_t whB = sbase + OFF_WH + (c & 3) * WTILE_B + w_lane_off;
        const uint32_t wlB = sbase + OFF_WL + (c & 3) * WTILE_B + w_lane_off;

#pragma unroll
        for (int ks = 0; ks < 4; ks++) {
            uint32_t bh[8], bl[8];
            ldm4(whB + (expCol0) * WROW_B + ks * 32, bh);            // experts +0..15
            ldm4(whB + (expCol0 + 16) * WROW_B + ks * 32, bh + 4);   // experts +16..31
            ldm4(wlB + (expCol0) * WROW_B + ks * 32, bl);
            ldm4(wlB + (expCol0 + 16) * WROW_B + ks * 32, bl + 4);

            uint32_t ah[2][4], al[2][4];
#pragma unroll
            for (int mt = 0; mt < 2; mt++) {
                int row = xrow0 + mt * 16;
                uint32_t cell = (uint32_t)(ks * 2 + xcellb);
                uint32_t off = row * 128 + ((cell ^ (row & 7)) << 4);
                ldm4(xh + off, ah[mt]);
                ldm4(xl + off, al[mt]);
            }
#pragma unroll
            for (int mt = 0; mt < 2; mt++)
#pragma unroll
                for (int nt = 0; nt < 4; nt++) {
                    const uint32_t* bhp = bh + (nt >> 1) * 4 + (nt & 1) * 2;
                    const uint32_t* blp = bl + (nt >> 1) * 4 + (nt & 1) * 2;
                    mma_bf16(acc[mt][nt], ah[mt], bhp);   // hi*hi
                    mma_bf16(acc[mt][nt], ah[mt], blp);   // hi*lo
                    mma_bf16(acc[mt][nt], al[mt], bhp);   // lo*hi
                }
        }

        // ---- split chunk c+1 (held in regs) into stage (c+1)&1 ----
        if (c + 1 < NCHUNK) {
            const uint32_t xh2 = sbase + OFF_XH + ((c + 1) & 1) * XSTG;
            const uint32_t xl2 = sbase + OFF_XL + ((c + 1) & 1) * XSTG;
#pragma unroll
            for (int j = 0; j < 4; j++) {
                uint32_t h0, l0, h1, l1, h2, l2, h3, l3;
                split_pair(st[2 * j].x, st[2 * j].y, h0, l0);
                split_pair(st[2 * j].z, st[2 * j].w, h1, l1);
                split_pair(st[2 * j + 1].x, st[2 * j + 1].y, h2, l2);
                split_pair(st[2 * j + 1].z, st[2 * j + 1].w, h3, l3);
                uint32_t off = srow * 128 + ((((uint32_t)(shalf * 4 + j)) ^ (srow & 7)) << 4);
                sts128(xh2 + off, h0, h1, h2, h3);
                sts128(xl2 + off, l0, l1, l2, l3);
            }
        }
        // ---- LDG chunk c+2 into regs ----
        if (c + 2 < NCHUNK) {
            const float* xp = xg + (c + 2) * BK;
#pragma unroll
            for (int j = 0; j < 8; j++) st[j] = *(const float4*)(xp + j * 4);
        }
    }

    // ---- epilogue ----
    __syncthreads();
    float* lt = (float*)smem;               // [128][65]
    float* rstats = lt + BM * 65;
#pragma unroll
    for (int mt = 0; mt < 2; mt++)
#pragma unroll
        for (int nt = 0; nt < 4; nt++) {
            int r0 = tokRow0 + mt * 16 + g;
            int cc = expCol0 + nt * 8 + 2 * t;
            lt[r0 * 65 + cc]           = acc[mt][nt][0];
            lt[r0 * 65 + cc + 1]       = acc[mt][nt][1];
            lt[(r0 + 8) * 65 + cc]     = acc[mt][nt][2];
            lt[(r0 + 8) * 65 + cc + 1] = acc[mt][nt][3];
        }
    __syncthreads();

    if (tid < BM) {
        const float* row = lt + tid * 65;
        float m1 = -1e30f, m2 = -1e30f;
        int i1 = 0, i2 = 0;
#pragma unroll 8
        for (int e = 0; e < NEXP; e++) {
            float v = row[e];
            if (v > m1) { m2 = m1; i2 = i1; m1 = v; i1 = e; }
            else if (v > m2) { m2 = v; i2 = e; }
        }
        float sum = 0.0f;
#pragma unroll 8
        for (int e = 0; e < NEXP; e++) sum += __expf(row[e] - m1);
        rstats[tid] = m1;
        rstats[BM + tid] = 1.0f / sum;

        float e2 = __expf(m2 - m1);
        float dn = 1.0f / (1.0f + e2);
        int gr = rowBase + tid;
        out_w[gr * TOPK + 0] = dn;
        out_w[gr * TOPK + 1] = e2 * dn;
        out_e[gr * TOPK + 0] = (float)i1;
        out_e[gr * TOPK + 1] = (float)i2;
    }
    __syncthreads();

    for (int i = tid; i < BM * NEXP; i += THREADS) {
        int r = i >> 6, cc = i & 63;
        out_scores[(size_t)(rowBase + r) * NEXP + cc] =
            __expf(lt[r * 65 + cc] - rstats[r]) * rstats[BM + r];
    }
}

extern "C" void kernel_launch(void* const* d_in, const int* in_sizes, int n_in,
                              void* d_out, int out_size) {
    const float* x = (const float*)d_in[0];   // [N, H] f32
    const float* W = (const float*)d_in[1];   // [E, H] f32

    float* out_scores = (float*)d_out;                      // N*E
    float* out_w      = out_scores + (size_t)NTOK * NEXP;   // N*TOPK
    float* out_e      = out_w + (size_t)NTOK * TOPK;        // N*TOPK

    cudaFuncSetAttribute(router_mma, cudaFuncAttributeMaxDynamicSharedMemorySize, SMEM_B);

    wsplit_kernel<<<(NEXP * HDIM) / 256, 256>>>(W);
    router_mma<<<NTOK / BM, THREADS, SMEM_B>>>(x, out_scores, out_w, out_e);
}

// round 9
// speedup vs baseline: 1.3550x; 1.3550x over previous
#include <cuda_runtime.h>
#include <cuda_bf16.h>
#include <cstdint>

#define NTOK 16384
#define HDIM 4096
#define NEXP 64
#define TOPK 2

#define BM 128
#define BK 64
#define NCHUNK (HDIM / BK)    // 64
#define NSTAGE 4
#define THREADS 512

// x tile: 128 rows x 256B (64 f32), 8B units XOR-swizzled within row
#define XTILE_B (BM * 256)              // 32768
// W tiles: 64 rows x 144B (128B data + 16B pad)
#define WROW_B 144
#define WTILE_B (NEXP * WROW_B)         // 9216
#define OFF_WH XTILE_B
#define OFF_WL (XTILE_B + WTILE_B)
#define STAGE_B (XTILE_B + 2 * WTILE_B) // 51200
#define SMEM_B (NSTAGE * STAGE_B)       // 204800

__device__ __nv_bfloat16 g_Wh[NEXP * HDIM];
__device__ __nv_bfloat16 g_Wl[NEXP * HDIM];

__device__ __forceinline__ uint32_t smem_u32(const void* p) {
    uint32_t a;
    asm("{ .reg .u64 t; cvta.to.shared.u64 t, %1; cvt.u32.u64 %0, t; }" : "=r"(a) : "l"(p));
    return a;
}

__device__ __forceinline__ void cpa16(uint32_t dst, const void* src) {
    asm volatile("cp.async.cg.shared.global [%0], [%1], 16;" :: "r"(dst), "l"(src) : "memory");
}

__device__ __forceinline__ void ldm4(uint32_t addr, uint32_t* r) {
    asm volatile("ldmatrix.sync.aligned.m8n8.x4.shared.b16 {%0,%1,%2,%3}, [%4];"
                 : "=r"(r[0]), "=r"(r[1]), "=r"(r[2]), "=r"(r[3]) : "r"(addr));
}

// split f32 pair into bf16x2 hi + bf16x2 lo (element0 in lo16)
__device__ __forceinline__ void split_pair(float f0, float f1, uint32_t& hi, uint32_t& lo) {
    asm("cvt.rn.bf16x2.f32 %0, %1, %2;" : "=r"(hi) : "f"(f1), "f"(f0));
    float h0 = __uint_as_float(hi << 16);
    float h1 = __uint_as_float(hi & 0xFFFF0000u);
    float l0 = f0 - h0;
    float l1 = f1 - h1;
    asm("cvt.rn.bf16x2.f32 %0, %1, %2;" : "=r"(lo) : "f"(l1), "f"(l0));
}

__device__ __forceinline__ void mma_bf16(float* d, const uint32_t* a, const uint32_t* b) {
    asm volatile(
        "mma.sync.aligned.m16n8k16.row.col.f32.bf16.bf16.f32 "
        "{%0,%1,%2,%3}, {%4,%5,%6,%7}, {%8,%9}, {%0,%1,%2,%3};"
        : "+f"(d[0]), "+f"(d[1]), "+f"(d[2]), "+f"(d[3])
        : "r"(a[0]), "r"(a[1]), "r"(a[2]), "r"(a[3]), "r"(b[0]), "r"(b[1]));
}

__global__ void wsplit_kernel(const float* __restrict__ W) {
    int i = blockIdx.x * blockDim.x + threadIdx.x;
    float w = W[i];
    __nv_bfloat16 h = __float2bfloat16(w);
    g_Wh[i] = h;
    g_Wl[i] = __float2bfloat16(w - __bfloat162float(h));
}

__device__ __forceinline__ void issue_chunk(uint32_t sbase, const float* __restrict__ x,
                                            int rowBase, int c, int tid) {
    const int s = c & (NSTAGE - 1);
    const uint32_t stb = sbase + s * STAGE_B;
    const int k0 = c * BK;
#pragma unroll
    for (int j = 0; j < 4; j++) {            // x: 2048 16B units
        int i = tid + j * THREADS;
        int row = i >> 4, q = i & 15;
        uint32_t d = stb + row * 256 + ((((2 * q) ^ ((row & 7) << 2))) << 3);
        cpa16(d, x + (size_t)(rowBase + row) * HDIM + k0 + q * 4);
    }
    {                                        // Wh + Wl: 512 units each
        int row = tid >> 3, q = tid & 7;
        cpa16(sbase + s * STAGE_B + OFF_WH + row * WROW_B + q * 16,
              g_Wh + (size_t)row * HDIM + k0 + q * 8);
        cpa16(sbase + s * STAGE_B + OFF_WL + row * WROW_B + q * 16,
              g_Wl + (size_t)row * HDIM + k0 + q * 8);
    }
    asm volatile("cp.async.commit_group;" ::: "memory");
}

__global__ __launch_bounds__(THREADS, 1)
void router_mma(const float* __restrict__ x,
                float* __restrict__ out_scores,
                float* __restrict__ out_w,
                float* __restrict__ out_e) {
    extern __shared__ char smem[];
    const uint32_t sbase = smem_u32(smem);
    const int tid = threadIdx.x;
    const int lane = tid & 31;
    const int wid = tid >> 5;        // 0..15
    const int grp = wid >> 3;        // 0: even chunks, 1: odd chunks
    const int widL = wid & 7;        // warp within group: owns rows widL*16.., all 64 experts
    const int g = lane >> 2;
    const int t = lane & 3;
    const int rowBase = blockIdx.x * BM;
    const int tokRow0 = widL * 16;

    // ldmatrix per-lane address offset within a W tile (expert block of 16)
    const int mtx = lane >> 3;
    const int rr = lane & 7;
    const uint32_t w_lane_off =
        (uint32_t)(((mtx >> 1) * 8 + rr) * WROW_B + (mtx & 1) * 16);

    float acc[8][4] = {};            // 64 experts x (16-row m-tile fragment)

    issue_chunk(sbase, x, rowBase, 0, tid);
    issue_chunk(sbase, x, rowBase, 1, tid);
    issue_chunk(sbase, x, rowBase, 2, tid);
    issue_chunk(sbase, x, rowBase, 3, tid);

    for (int cc = 0; cc < NCHUNK; cc += 2) {
        if (cc + 2 < NCHUNK) {
            asm volatile("cp.async.wait_group 2;" ::: "memory");
        } else {
            asm volatile("cp.async.wait_group 0;" ::: "memory");
        }
        __syncthreads();     // chunks cc, cc+1 visible to all

        // ---- compute: group grp handles chunk cc+grp ----
        {
            const int c = cc + grp;
            const int s = c & (NSTAGE - 1);
            const uint32_t stb = sbase + s * STAGE_B;
            const char* xs = smem + s * STAGE_B;
            const uint32_t whA = stb + OFF_WH + w_lane_off;
            const uint32_t wlA = stb + OFF_WL + w_lane_off;

#pragma unroll
            for (int ks = 0; ks < 4; ks++) {
                // ---- A fragment: one m16 tile, split f32 -> bf16 hi/lo ----
                uint32_t u0 = ((uint32_t)(ks * 8 + t) ^ ((uint32_t)g << 2)) << 3;
                uint32_t u4 = u0 ^ 32;
                const char* xr0 = xs + (tokRow0 + g) * 256;
                const char* xr1 = xr0 + 8 * 256;
                float2 f00 = *(const float2*)(xr0 + u0);
                float2 f10 = *(const float2*)(xr1 + u0);
                float2 f02 = *(const float2*)(xr0 + u4);
                float2 f12 = *(const float2*)(xr1 + u4);
                uint32_t ah[4], al[4];
                split_pair(f00.x, f00.y, ah[0], al[0]);
                split_pair(f10.x, f10.y, ah[1], al[1]);
                split_pair(f02.x, f02.y, ah[2], al[2]);
                split_pair(f12.x, f12.y, ah[3], al[3]);

                // ---- expert halves: keep fragment liveness low ----
#pragma unroll
                for (int eh = 0; eh < 2; eh++) {
                    uint32_t bh[8], bl[8];
                    ldm4(whA + (eh * 32) * WROW_B + ks * 32, bh);
                    ldm4(whA + (eh * 32 + 16) * WROW_B + ks * 32, bh + 4);
                    ldm4(wlA + (eh * 32) * WROW_B + ks * 32, bl);
                    ldm4(wlA + (eh * 32 + 16) * WROW_B + ks * 32, bl + 4);
#pragma unroll
                    for (int nt = 0; nt < 4; nt++) {
                        float* ac = acc[eh * 4 + nt];
                        const uint32_t* bhp = bh + (nt >> 1) * 4 + (nt & 1) * 2;
                        const uint32_t* blp = bl + (nt >> 1) * 4 + (nt & 1) * 2;
                        mma_bf16(ac, ah, bhp);   // hi*hi
                        mma_bf16(ac, ah, blp);   // hi*lo
                        mma_bf16(ac, al, bhp);   // lo*hi (lo*lo dropped)
                    }
                }
            }
        }
        __syncthreads();     // all reads of stages (cc..cc+1..cc+3) settled before overwrite

        if (cc + 4 < NCHUNK) issue_chunk(sbase, x, rowBase, cc + 4, tid);
        if (cc + 5 < NCHUNK) issue_chunk(sbase, x, rowBase, cc + 5, tid);
    }

    // ---- epilogue: merge the two parity groups' partials ----
    __syncthreads();
    float* lt = (float*)smem;               // [128][65]
    float* rstats = lt + BM * 65;

    if (grp == 1) {
#pragma unroll
        for (int nt = 0; nt < 8; nt++) {
            int r0 = tokRow0 + g;
            int cc2 = nt * 8 + 2 * t;
            lt[r0 * 65 + cc2]           = acc[nt][0];
            lt[r0 * 65 + cc2 + 1]       = acc[nt][1];
            lt[(r0 + 8) * 65 + cc2]     = acc[nt][2];
            lt[(r0 + 8) * 65 + cc2 + 1] = acc[nt][3];
        }
    }
    __syncthreads();
    if (grp == 0) {
#pragma unroll
        for (int nt = 0; nt < 8; nt++) {
            int r0 = tokRow0 + g;
            int cc2 = nt * 8 + 2 * t;
            lt[r0 * 65 + cc2]           += acc[nt][0];
            lt[r0 * 65 + cc2 + 1]       += acc[nt][1];
            lt[(r0 + 8) * 65 + cc2]     += acc[nt][2];
            lt[(r0 + 8) * 65 + cc2 + 1] += acc[nt][3];
        }
    }
    __syncthreads();

    if (tid < BM) {
        const float* row = lt + tid * 65;
        float m1 = -1e30f, m2 = -1e30f;
        int i1 = 0, i2 = 0;
#pragma unroll 8
        for (int e = 0; e < NEXP; e++) {
            float v = row[e];
            if (v > m1) { m2 = m1; i2 = i1; m1 = v; i1 = e; }
            else if (v > m2) { m2 = v; i2 = e; }
        }
        float sum = 0.0f;
#pragma unroll 8
        for (int e = 0; e < NEXP; e++) sum += __expf(row[e] - m1);
        rstats[tid] = m1;
        rstats[BM + tid] = 1.0f / sum;

        float e2 = __expf(m2 - m1);
        float dn = 1.0f / (1.0f + e2);
        int gr = rowBase + tid;
        out_w[gr * TOPK + 0] = dn;
        out_w[gr * TOPK + 1] = e2 * dn;
        out_e[gr * TOPK + 0] = (float)i1;
        out_e[gr * TOPK + 1] = (float)i2;
    }
    __syncthreads();

    for (int i = tid; i < BM * NEXP; i += THREADS) {
        int r = i >> 6, cc2 = i & 63;
        out_scores[(size_t)(rowBase + r) * NEXP + cc2] =
            __expf(lt[r * 65 + cc2] - rstats[r]) * rstats[BM + r];
    }
}

extern "C" void kernel_launch(void* const* d_in, const int* in_sizes, int n_in,
                              void* d_out, int out_size) {
    const float* x = (const float*)d_in[0];   // [N, H] f32
    const float* W = (const float*)d_in[1];   // [E, H] f32

    float* out_scores = (float*)d_out;                      // N*E
    float* out_w      = out_scores + (size_t)NTOK * NEXP;   // N*TOPK
    float* out_e      = out_w + (size_t)NTOK * TOPK;        // N*TOPK

    cudaFuncSetAttribute(router_mma, cudaFuncAttributeMaxDynamicSharedMemorySize, SMEM_B);

    wsplit_kernel<<<(NEXP * HDIM) / 256, 256>>>(W);
    router_mma<<<NTOK / BM, THREADS, SMEM_B>>>(x, out_scores, out_w, out_e);
}

// round 10
// speedup vs baseline: 1.4154x; 1.0445x over previous
#include <cuda_runtime.h>
#include <cuda_bf16.h>
#include <cstdint>

#define NTOK 16384
#define HDIM 4096
#define NEXP 64
#define TOPK 2

#define BM 128
#define BK 64
#define NCHUNK (HDIM / BK)    // 64
#define NSTAGE 4
#define THREADS 256

// x tile: 128 rows x 256B (64 f32), 8B units XOR-swizzled within row
#define XTILE_B (BM * 256)              // 32768
// W tiles: 64 rows x 144B (128B data + 16B pad)
#define WROW_B 144
#define WTILE_B (NEXP * WROW_B)         // 9216
#define OFF_WH XTILE_B
#define OFF_WL (XTILE_B + WTILE_B)
#define STAGE_B (XTILE_B + 2 * WTILE_B) // 51200
#define SMEM_B (NSTAGE * STAGE_B)       // 204800

__device__ __nv_bfloat16 g_Wh[NEXP * HDIM];
__device__ __nv_bfloat16 g_Wl[NEXP * HDIM];

__device__ __forceinline__ uint32_t smem_u32(const void* p) {
    uint32_t a;
    asm("{ .reg .u64 t; cvta.to.shared.u64 t, %1; cvt.u32.u64 %0, t; }" : "=r"(a) : "l"(p));
    return a;
}

__device__ __forceinline__ void cpa16(uint32_t dst, const void* src) {
    asm volatile("cp.async.cg.shared.global [%0], [%1], 16;" :: "r"(dst), "l"(src) : "memory");
}

__device__ __forceinline__ void ldm4(uint32_t addr, uint32_t* r) {
    asm volatile("ldmatrix.sync.aligned.m8n8.x4.shared.b16 {%0,%1,%2,%3}, [%4];"
                 : "=r"(r[0]), "=r"(r[1]), "=r"(r[2]), "=r"(r[3]) : "r"(addr));
}

// split f32 pair into bf16x2 hi + bf16x2 lo (element0 in lo16)
__device__ __forceinline__ void split_pair(float f0, float f1, uint32_t& hi, uint32_t& lo) {
    asm("cvt.rn.bf16x2.f32 %0, %1, %2;" : "=r"(hi) : "f"(f1), "f"(f0));
    float h0 = __uint_as_float(hi << 16);
    float h1 = __uint_as_float(hi & 0xFFFF0000u);
    float l0 = f0 - h0;
    float l1 = f1 - h1;
    asm("cvt.rn.bf16x2.f32 %0, %1, %2;" : "=r"(lo) : "f"(l1), "f"(l0));
}

__device__ __forceinline__ void mma_bf16(float* d, const uint32_t* a, const uint32_t* b) {
    asm volatile(
        "mma.sync.aligned.m16n8k16.row.col.f32.bf16.bf16.f32 "
        "{%0,%1,%2,%3}, {%4,%5,%6,%7}, {%8,%9}, {%0,%1,%2,%3};"
        : "+f"(d[0]), "+f"(d[1]), "+f"(d[2]), "+f"(d[3])
        : "r"(a[0]), "r"(a[1]), "r"(a[2]), "r"(a[3]), "r"(b[0]), "r"(b[1]));
}

__global__ void wsplit_kernel(const float* __restrict__ W) {
    int i = blockIdx.x * blockDim.x + threadIdx.x;
    float w = W[i];
    __nv_bfloat16 h = __float2bfloat16(w);
    g_Wh[i] = h;
    g_Wl[i] = __float2bfloat16(w - __bfloat162float(h));
}

__device__ __forceinline__ void issue_chunk(uint32_t sbase, const float* __restrict__ x,
                                            int rowBase, int c, int tid) {
    const int s = c & (NSTAGE - 1);
    const uint32_t stb = sbase + s * STAGE_B;
    const int k0 = c * BK;
#pragma unroll
    for (int j = 0; j < 8; j++) {            // x: 2048 16B units
        int i = tid + j * THREADS;
        int row = i >> 4, q = i & 15;
        uint32_t d = stb + row * 256 + ((((2 * q) ^ ((row & 7) << 2))) << 3);
        cpa16(d, x + (size_t)(rowBase + row) * HDIM + k0 + q * 4);
    }
#pragma unroll
    for (int j = 0; j < 2; j++) {            // Wh + Wl: 512 units each
        int i = tid + j * THREADS;
        int row = i >> 3, q = i & 7;
        cpa16(stb + OFF_WH + row * WROW_B + q * 16, g_Wh + (size_t)row * HDIM + k0 + q * 8);
        cpa16(stb + OFF_WL + row * WROW_B + q * 16, g_Wl + (size_t)row * HDIM + k0 + q * 8);
    }
    asm volatile("cp.async.commit_group;" ::: "memory");
}

__global__ __launch_bounds__(THREADS, 1)
void router_mma(const float* __restrict__ x,
                float* __restrict__ out_scores,
                float* __restrict__ out_w,
                float* __restrict__ out_e) {
    extern __shared__ char smem[];
    const uint32_t sbase = smem_u32(smem);
    const int tid = threadIdx.x;
    const int lane = tid & 31;
    const int wid = tid >> 5;        // 0..7: warp owns rows wid*16..wid*16+15, ALL 64 experts
    const int g = lane >> 2;         // 0..7
    const int t = lane & 3;          // 0..3
    const int rowBase = blockIdx.x * BM;
    const int tokRow0 = wid * 16;

    // ldmatrix per-lane address offset within a W tile (expert block 0..15)
    const int mtx = lane >> 3;       // matrix index 0..3
    const int rr = lane & 7;
    const uint32_t w_lane_off =
        (uint32_t)(((mtx >> 1) * 8 + rr) * WROW_B + (mtx & 1) * 16);

    float accm[8][4] = {};           // hi*hi accumulators (independent)
    float accc[8][4] = {};           // correction accumulators (hi*lo + lo*hi)

    issue_chunk(sbase, x, rowBase, 0, tid);
    issue_chunk(sbase, x, rowBase, 1, tid);
    issue_chunk(sbase, x, rowBase, 2, tid);

    for (int c = 0; c < NCHUNK; c++) {
        const int s = c & (NSTAGE - 1);
        if (c <= NCHUNK - 3) {
            asm volatile("cp.async.wait_group 2;" ::: "memory");
        } else if (c == NCHUNK - 2) {
            asm volatile("cp.async.wait_group 1;" ::: "memory");
        } else {
            asm volatile("cp.async.wait_group 0;" ::: "memory");
        }
        __syncthreads();   // stage-c visible; stage (c+3)%4 free

        if (c + 3 < NCHUNK) issue_chunk(sbase, x, rowBase, c + 3, tid);

        const uint32_t stb = sbase + s * STAGE_B;
        const char* xs = smem + s * STAGE_B;
        const uint32_t whA = stb + OFF_WH + w_lane_off;
        const uint32_t wlA = stb + OFF_WL + w_lane_off;

#pragma unroll
        for (int ks = 0; ks < 4; ks++) {
            // ---- B fragments via ldmatrix.x4: all 64 experts, hi + lo ----
            uint32_t bh[16], bl[16];             // [e*4 + m], e = expert block of 16
#pragma unroll
            for (int e = 0; e < 4; e++)
                ldm4(whA + e * (16 * WROW_B) + ks * 32, bh + e * 4);
#pragma unroll
            for (int e = 0; e < 4; e++)
                ldm4(wlA + e * (16 * WROW_B) + ks * 32, bl + e * 4);

            // ---- A fragment: one m16 tile, split f32 -> bf16 hi/lo ----
            uint32_t u0 = ((uint32_t)(ks * 8 + t) ^ ((uint32_t)g << 2)) << 3;
            uint32_t u4 = u0 ^ 32;
            const char* xr0 = xs + (tokRow0 + g) * 256;
            const char* xr1 = xr0 + 8 * 256;
            float2 f00 = *(const float2*)(xr0 + u0);
            float2 f10 = *(const float2*)(xr1 + u0);
            float2 f02 = *(const float2*)(xr0 + u4);
            float2 f12 = *(const float2*)(xr1 + u4);
            uint32_t ah[4], al[4];
            split_pair(f00.x, f00.y, ah[0], al[0]);
            split_pair(f10.x, f10.y, ah[1], al[1]);
            split_pair(f02.x, f02.y, ah[2], al[2]);
            split_pair(f12.x, f12.y, ah[3], al[3]);

            // ---- three sweeps of 8 independent HMMAs: no RAW chains ----
#pragma unroll
            for (int nt = 0; nt < 8; nt++)
                mma_bf16(accm[nt], ah, bh + (nt >> 1) * 4 + (nt & 1) * 2);   // hi*hi
#pragma unroll
            for (int nt = 0; nt < 8; nt++)
                mma_bf16(accc[nt], ah, bl + (nt >> 1) * 4 + (nt & 1) * 2);   // hi*lo
#pragma unroll
            for (int nt = 0; nt < 8; nt++)
                mma_bf16(accc[nt], al, bh + (nt >> 1) * 4 + (nt & 1) * 2);   // lo*hi
        }
    }

    // ---- epilogue: merge accm+accc, spill logits to smem ----
    __syncthreads();
    float* lt = (float*)smem;               // [128][65]
    float* rstats = lt + BM * 65;
#pragma unroll
    for (int nt = 0; nt < 8; nt++) {
        int r0 = tokRow0 + g;
        int cc = nt * 8 + 2 * t;
        lt[r0 * 65 + cc]           = accm[nt][0] + accc[nt][0];
        lt[r0 * 65 + cc + 1]       = accm[nt][1] + accc[nt][1];
        lt[(r0 + 8) * 65 + cc]     = accm[nt][2] + accc[nt][2];
        lt[(r0 + 8) * 65 + cc + 1] = accm[nt][3] + accc[nt][3];
    }
    __syncthreads();

    if (tid < BM) {
        const float* row = lt + tid * 65;
        float m1 = -1e30f, m2 = -1e30f;
        int i1 = 0, i2 = 0;
#pragma unroll 8
        for (int e = 0; e < NEXP; e++) {
            float v = row[e];
            if (v > m1) { m2 = m1; i2 = i1; m1 = v; i1 = e; }
            else if (v > m2) { m2 = v; i2 = e; }
        }
        float sum = 0.0f;
#pragma unroll 8
        for (int e = 0; e < NEXP; e++) sum += __expf(row[e] - m1);
        rstats[tid] = m1;
        rstats[BM + tid] = 1.0f / sum;

        float e2 = __expf(m2 - m1);
        float dn = 1.0f / (1.0f + e2);
        int gr = rowBase + tid;
        out_w[gr * TOPK + 0] = dn;
        out_w[gr * TOPK + 1] = e2 * dn;
        out_e[gr * TOPK + 0] = (float)i1;
        out_e[gr * TOPK + 1] = (float)i2;
    }
    __syncthreads();

    for (int i = tid; i < BM * NEXP; i += THREADS) {
        int r = i >> 6, cc = i & 63;
        out_scores[(size_t)(rowBase + r) * NEXP + cc] =
            __expf(lt[r * 65 + cc] - rstats[r]) * rstats[BM + r];
    }
}

extern "C" void kernel_launch(void* const* d_in, const int* in_sizes, int n_in,
                              void* d_out, int out_size) {
    const float* x = (const float*)d_in[0];   // [N, H] f32
    const float* W = (const float*)d_in[1];   // [E, H] f32

    float* out_scores = (float*)d_out;                      // N*E
    float* out_w      = out_scores + (size_t)NTOK * NEXP;   // N*TOPK
    float* out_e      = out_w + (size_t)NTOK * TOPK;        // N*TOPK

    cudaFuncSetAttribute(router_mma, cudaFuncAttributeMaxDynamicSharedMemorySize, SMEM_B);

    wsplit_kernel<<<(NEXP * HDIM) / 256, 256>>>(W);
    router_mma<<<NTOK / BM, THREADS, SMEM_B>>>(x, out_scores, out_w, out_e);
}